// round 1
// baseline (speedup 1.0000x reference)
#include <cuda_runtime.h>

// YOLOv2 region loss, fused single pass + scalar reduction.
// B=16, A=5, C=80, H=W=64, N_GT=50, STRIDE=16, THRESH=0.6
// obj_scale=5, noobj=1, coord=1, class=1.

#define NA 5
#define NC 80
#define NGT 50
#define NB 16
#define HH 64
#define WW 64
#define HW 4096          // H*W
#define CH 85            // 5 + C

__device__ double g_acc;

__global__ void rl_init_kernel() { g_acc = 0.0; }

__global__ void rl_final_kernel(float* out) { out[0] = (float)g_acc; }

__global__ __launch_bounds__(256) void rl_loss_kernel(
    const float* __restrict__ outp,
    const float* __restrict__ target,
    const float* __restrict__ anchors)
{
    // GT boxes for this batch, shared by the whole block
    __shared__ float s_x1[NGT], s_y1[NGT], s_x2[NGT], s_y2[NGT], s_area[NGT];
    __shared__ float s_cx[NGT], s_cy[NGT], s_w[NGT], s_h[NGT], s_cls[NGT];

    const int cell = blockIdx.x * 256 + threadIdx.x;
    const int ba   = cell >> 12;         // b*A + a   (4096 cells per (b,a); 256 | 4096)
    const int b    = ba / NA;
    const int a    = ba - b * NA;
    const int hw   = cell & (HW - 1);
    const int h    = hw >> 6;
    const int w    = hw & (WW - 1);

    if (threadIdx.x < NGT) {
        const float* t = target + ((size_t)b * NGT + threadIdx.x) * 5;
        float cls = t[0], cx = t[1], cy = t[2], gw = t[3], gh = t[4];
        float x1 = cx - gw * 0.5f, y1 = cy - gh * 0.5f;
        float x2 = cx + gw * 0.5f, y2 = cy + gh * 0.5f;
        s_x1[threadIdx.x] = x1;  s_y1[threadIdx.x] = y1;
        s_x2[threadIdx.x] = x2;  s_y2[threadIdx.x] = y2;
        s_area[threadIdx.x] = (x2 - x1) * (y2 - y1);   // match reference: area from corners
        s_cx[threadIdx.x] = cx;  s_cy[threadIdx.x] = cy;
        s_w[threadIdx.x]  = gw;  s_h[threadIdx.x]  = gh;
        s_cls[threadIdx.x] = cls;
    }
    __syncthreads();

    // channel c of cell (b,a,h,w) lives at ((b*A + a)*85 + c)*4096 + h*64 + w
    const float* base = outp + ((size_t)ba * CH) * HW + hw;
    const float t0   = base[0];
    const float t1   = base[HW];
    const float t2   = base[2 * HW];
    const float t3   = base[3 * HW];
    const float conf = base[4 * HW];

    const float aw = anchors[2 * a];
    const float ah = anchors[2 * a + 1];

    const float px = (1.0f / (1.0f + expf(-t0)) + (float)w) * 16.0f;
    const float py = (1.0f / (1.0f + expf(-t1)) + (float)h) * 16.0f;
    const float pw = expf(t2) * aw;
    const float ph = expf(t3) * ah;

    const float px1 = px - pw * 0.5f, py1 = py - ph * 0.5f;
    const float px2 = px + pw * 0.5f, py2 = py + ph * 0.5f;
    const float parea = (px2 - px1) * (py2 - py1);

    // argmax over 50 GTs via cross-multiplication (strict > keeps first occurrence,
    // matching jnp.argmax; all unions are strictly positive)
    float bi = -1.0f, bu = 1.0f;
    int bidx = 0;
#pragma unroll 10
    for (int n = 0; n < NGT; n++) {
        float ix1 = fmaxf(s_x1[n], px1);
        float iy1 = fmaxf(s_y1[n], py1);
        float ix2 = fminf(s_x2[n], px2);
        float iy2 = fminf(s_y2[n], py2);
        float inter = fmaxf(ix2 - ix1, 0.0f) * fmaxf(iy2 - iy1, 0.0f);
        float uni = s_area[n] + parea - inter + 1e-6f;
        if (inter * bu > bi * uni) { bi = inter; bu = uni; bidx = n; }
    }
    const float best_iou = bi / bu;

    float loss;
    if (best_iou > 0.6f) {
        // coord loss (raw logits vs pixel-space gt, exactly as reference does)
        float d0 = t0 - s_cx[bidx];
        float d1 = t1 - s_cy[bidx];
        float d2 = t2 - s_w[bidx];
        float d3 = t3 - s_h[bidx];
        float dc = 5.0f * conf - 5.0f;             // obj: (5*conf - 5)^2
        loss = d0 * d0 + d1 * d1 + d2 * d2 + d3 * d3 + dc * dc;

        // class NLL: -(logit[idx] - log(sum exp(logit))); logits ~N(0,1) so the
        // unshifted logsumexp is numerically safe (max exp ~ e^5)
        int idx = (int)s_cls[bidx];
        const float* cl = base + (size_t)5 * HW;
        float ssum = 0.0f;
        float lt = 0.0f;
        for (int c = 0; c < NC; c++) {
            float l = cl[(size_t)c * HW];
            ssum += expf(l);
            if (c == idx) lt = l;
        }
        loss += logf(ssum) - lt;
    } else {
        loss = conf * conf;                        // noobj: (1*conf - 0)^2
    }

    // block reduction -> one double atomic per block
    double v = (double)loss;
    #pragma unroll
    for (int off = 16; off; off >>= 1)
        v += __shfl_down_sync(0xffffffffu, v, off);

    __shared__ double s_red[8];
    const int lane = threadIdx.x & 31;
    const int wid  = threadIdx.x >> 5;
    if (lane == 0) s_red[wid] = v;
    __syncthreads();
    if (wid == 0) {
        v = (lane < 8) ? s_red[lane] : 0.0;
        #pragma unroll
        for (int off = 4; off; off >>= 1)
            v += __shfl_down_sync(0xffu, v, off);
        if (lane == 0) atomicAdd(&g_acc, v);
    }
}

extern "C" void kernel_launch(void* const* d_in, const int* in_sizes, int n_in,
                              void* d_out, int out_size)
{
    const float* outp    = (const float*)d_in[0];
    const float* target  = (const float*)d_in[1];
    const float* anchors = (const float*)d_in[2];
    float* out = (float*)d_out;

    rl_init_kernel<<<1, 1>>>();
    const int cells = NB * NA * HH * WW;           // 327680
    rl_loss_kernel<<<cells / 256, 256>>>(outp, target, anchors);
    rl_final_kernel<<<1, 1>>>(out);
}

// round 2
// speedup vs baseline: 1.0873x; 1.0873x over previous
#include <cuda_runtime.h>

// YOLOv2 region loss, single fused kernel (last-block reduction).
// B=16, A=5, C=80, H=W=64, N_GT=50, STRIDE=16, THRESH=0.6

#define NA 5
#define NC 80
#define NGT 50
#define NB 16
#define HH 64
#define WW 64
#define HW 4096
#define CH 85
#define NBLOCKS 1280     // (16*5*4096)/256

__device__ double g_part[NBLOCKS];
__device__ unsigned int g_flag;   // zero at load; last block resets to 0 each launch

__global__ __launch_bounds__(256) void rl_loss_kernel(
    const float* __restrict__ outp,
    const float* __restrict__ target,
    const float* __restrict__ anchors,
    float* __restrict__ out)
{
    // GT boxes for this batch, shared by the whole block
    __shared__ float4 s_box[NGT];              // x1,y1,x2,y2
    __shared__ float  s_sa[NGT];               // gt area
    __shared__ float4 s_gt[NGT];               // cx,cy,w,h (for coord loss)
    __shared__ float  s_cls[NGT];
    __shared__ double s_red[8];
    __shared__ int    s_last;

    const int cell = blockIdx.x * 256 + threadIdx.x;
    const int ba   = cell >> 12;               // b*A + a  (4096 cells per (b,a))
    const int b    = ba / NA;
    const int a    = ba - b * NA;
    const int hw   = cell & (HW - 1);
    const int h    = hw >> 6;
    const int w    = hw & (WW - 1);

    if (threadIdx.x < NGT) {
        const float* t = target + ((size_t)b * NGT + threadIdx.x) * 5;
        float cls = t[0], cx = t[1], cy = t[2], gw = t[3], gh = t[4];
        float x1 = cx - gw * 0.5f, y1 = cy - gh * 0.5f;
        float x2 = cx + gw * 0.5f, y2 = cy + gh * 0.5f;
        s_box[threadIdx.x] = make_float4(x1, y1, x2, y2);
        s_sa[threadIdx.x]  = (x2 - x1) * (y2 - y1);
        s_gt[threadIdx.x]  = make_float4(cx, cy, gw, gh);
        s_cls[threadIdx.x] = cls;
    }
    __syncthreads();

    // channel c of cell (b,a,h,w): ((b*A+a)*85 + c)*4096 + hw
    const float* base = outp + ((size_t)ba * CH) * HW + hw;
    const float t0   = base[0];
    const float t1   = base[HW];
    const float t2   = base[2 * HW];
    const float t3   = base[3 * HW];
    const float conf = base[4 * HW];

    const float aw = anchors[2 * a];
    const float ah = anchors[2 * a + 1];

    // fast sigmoid/exp: MUFU.EX2-backed, error ~2^-21 (boxes in [0,1024] px)
    const float sx = __fdividef(1.0f, 1.0f + __expf(-t0));
    const float sy = __fdividef(1.0f, 1.0f + __expf(-t1));
    const float px = (sx + (float)w) * 16.0f;
    const float py = (sy + (float)h) * 16.0f;
    const float pw = __expf(t2) * aw;
    const float ph = __expf(t3) * ah;

    const float px1 = px - pw * 0.5f, py1 = py - ph * 0.5f;
    const float px2 = px + pw * 0.5f, py2 = py + ph * 0.5f;
    const float pa  = (px2 - px1) * (py2 - py1) + 1e-6f;   // pred area + eps

    // argmax_n  I_n / S_n   where S_n = sa_n + pa (+eps).  iou = r/(1-r) is
    // strictly monotone in r = I/S, so argmax and the >0.6 test both transfer.
    float bI = -1.0f, bS = 1.0f;
    int bidx = 0;
#pragma unroll 10
    for (int n = 0; n < NGT; n++) {
        float4 bx = s_box[n];
        float dx = fminf(bx.z, px2) - fmaxf(bx.x, px1);
        float dy = fminf(bx.w, py2) - fmaxf(bx.y, py1);
        float I  = fmaxf(dx, 0.0f) * fmaxf(dy, 0.0f);
        float S  = s_sa[n] + pa;
        if (I * bS > bI * S) { bI = I; bS = S; bidx = n; }
    }

    // best_iou > 0.6  ⇔  bI/(bS-bI) > 0.6  ⇔  8*bI > 3*bS   (bS-bI = union > 0)
    float loss;
    if (8.0f * bI > 3.0f * bS) {
        float4 g = s_gt[bidx];
        float d0 = t0 - g.x;
        float d1 = t1 - g.y;
        float d2 = t2 - g.z;
        float d3 = t3 - g.w;
        float dc = 5.0f * conf - 5.0f;
        loss = d0 * d0 + d1 * d1 + d2 * d2 + d3 * d3 + dc * dc;

        // class NLL (logits ~N(0,1): unshifted logsumexp is safe)
        int idx = (int)s_cls[bidx];
        const float* cl = base + (size_t)5 * HW;
        float ssum = 0.0f, lt = 0.0f;
        for (int c = 0; c < NC; c++) {
            float l = cl[(size_t)c * HW];
            ssum += __expf(l);
            if (c == idx) lt = l;
        }
        loss += __logf(ssum) - lt;
    } else {
        loss = conf * conf;
    }

    // block reduction in double
    double v = (double)loss;
    #pragma unroll
    for (int off = 16; off; off >>= 1)
        v += __shfl_down_sync(0xffffffffu, v, off);

    const int lane = threadIdx.x & 31;
    const int wid  = threadIdx.x >> 5;
    if (lane == 0) s_red[wid] = v;
    __syncthreads();
    if (threadIdx.x < 32) {
        v = (lane < 8) ? s_red[lane] : 0.0;
        #pragma unroll
        for (int off = 4; off; off >>= 1)
            v += __shfl_down_sync(0xffu, v, off);
    }

    // last-block-reduces pattern (no separate init/final launches)
    if (threadIdx.x == 0) {
        g_part[blockIdx.x] = v;
        __threadfence();
        unsigned int done = atomicAdd(&g_flag, 1u);
        s_last = (done == NBLOCKS - 1);
    }
    __syncthreads();

    if (s_last) {
        double t = 0.0;
        for (int i = threadIdx.x; i < NBLOCKS; i += 256)
            t += g_part[i];
        #pragma unroll
        for (int off = 16; off; off >>= 1)
            t += __shfl_down_sync(0xffffffffu, t, off);
        if (lane == 0) s_red[wid] = t;
        __syncthreads();
        if (threadIdx.x == 0) {
            double tot = 0.0;
            #pragma unroll
            for (int i = 0; i < 8; i++) tot += s_red[i];
            out[0] = (float)tot;
            atomicExch(&g_flag, 0u);      // reset for next graph replay
        }
    }
}

extern "C" void kernel_launch(void* const* d_in, const int* in_sizes, int n_in,
                              void* d_out, int out_size)
{
    const float* outp    = (const float*)d_in[0];
    const float* target  = (const float*)d_in[1];
    const float* anchors = (const float*)d_in[2];
    float* out = (float*)d_out;

    rl_loss_kernel<<<NBLOCKS, 256>>>(outp, target, anchors, out);
}

// round 3
// speedup vs baseline: 1.0957x; 1.0077x over previous
#include <cuda_runtime.h>

// YOLOv2 region loss, single fused kernel.
// Phase 1: select-free "any GT passes 0.6" test via max of (8I - 3S).
// Phase 2 (rare masked lanes): exact cross-multiplied argmax + coord/class loss.

#define NA 5
#define NC 80
#define NGT 50
#define NB 16
#define HW 4096
#define CH 85
#define NBLOCKS 1280     // (16*5*4096)/256

__device__ double g_part[NBLOCKS];
__device__ unsigned int g_flag;   // zero-init; last block resets each launch

__global__ __launch_bounds__(256) void rl_loss_kernel(
    const float* __restrict__ outp,
    const float* __restrict__ target,
    const float* __restrict__ anchors,
    float* __restrict__ out)
{
    __shared__ float4 s_box[NGT];      // x1,y1,x2,y2
    __shared__ float  s_m3sa[NGT];     // -3 * gt_area
    __shared__ float4 s_gt[NGT];       // cx,cy,w,h
    __shared__ float  s_cls[NGT];
    __shared__ double s_red[8];
    __shared__ int    s_last;

    const int cell = blockIdx.x * 256 + threadIdx.x;
    const int ba   = cell >> 12;               // b*A + a
    const int b    = ba / NA;
    const int a    = ba - b * NA;
    const int hw   = cell & (HW - 1);
    const int h    = hw >> 6;
    const int w    = hw & 63;

    if (threadIdx.x < NGT) {
        const float* t = target + ((size_t)b * NGT + threadIdx.x) * 5;
        float cls = t[0], cx = t[1], cy = t[2], gw = t[3], gh = t[4];
        float x1 = cx - gw * 0.5f, y1 = cy - gh * 0.5f;
        float x2 = cx + gw * 0.5f, y2 = cy + gh * 0.5f;
        s_box[threadIdx.x]  = make_float4(x1, y1, x2, y2);
        s_m3sa[threadIdx.x] = -3.0f * ((x2 - x1) * (y2 - y1));
        s_gt[threadIdx.x]   = make_float4(cx, cy, gw, gh);
        s_cls[threadIdx.x]  = cls;
    }
    __syncthreads();

    // channel c of cell (b,a,h,w): ((b*A+a)*85 + c)*4096 + hw
    const float* base = outp + ((size_t)ba * CH) * HW + hw;
    const float t0   = base[0];
    const float t1   = base[HW];
    const float t2   = base[2 * HW];
    const float t3   = base[3 * HW];
    const float conf = base[4 * HW];

    const float aw = anchors[2 * a];
    const float ah = anchors[2 * a + 1];

    const float sx = __fdividef(1.0f, 1.0f + __expf(-t0));
    const float sy = __fdividef(1.0f, 1.0f + __expf(-t1));
    const float px = (sx + (float)w) * 16.0f;
    const float py = (sy + (float)h) * 16.0f;
    const float pw = __expf(t2) * aw;
    const float ph = __expf(t3) * ah;

    const float px1 = px - pw * 0.5f, py1 = py - ph * 0.5f;
    const float px2 = px + pw * 0.5f, py2 = py + ph * 0.5f;
    const float pa  = (px2 - px1) * (py2 - py1);
    const float cpa = -3.0f * (pa + 1e-6f);    // -3*(pred_area + eps)

    // ---- Phase 1: mask test only.  iou_n>0.6 <=> 8*I_n - 3*S_n > 0,
    // S_n = gt_area + pred_area + 1e-6.  mask <=> max_n key_n > 0.
    float mk0 = -1e30f, mk1 = -1e30f;
#pragma unroll 10
    for (int n = 0; n < NGT; n += 2) {
        float4 b0 = s_box[n];
        float4 b1 = s_box[n + 1];
        float cw0 = fminf(b0.z, px2) - fmaxf(b0.x, px1);
        float ch0 = fminf(b0.w, py2) - fmaxf(b0.y, py1);
        float cw1 = fminf(b1.z, px2) - fmaxf(b1.x, px1);
        float ch1 = fminf(b1.w, py2) - fmaxf(b1.y, py1);
        float I0 = fmaxf(cw0, 0.0f) * fmaxf(ch0, 0.0f);
        float I1 = fmaxf(cw1, 0.0f) * fmaxf(ch1, 0.0f);
        float k0 = fmaf(I0, 8.0f, s_m3sa[n] + cpa);
        float k1 = fmaf(I1, 8.0f, s_m3sa[n + 1] + cpa);
        mk0 = fmaxf(mk0, k0);
        mk1 = fmaxf(mk1, k1);
    }

    float loss;
    if (fmaxf(mk0, mk1) > 0.0f) {
        // ---- Phase 2 (rare): exact argmax over I/S via cross-multiplication
        // (monotone-equivalent to iou = I/(S-I); strict > keeps first index).
        float bI = -1.0f, bS = 1.0f;
        int bidx = 0;
        const float paeps = pa + 1e-6f;
#pragma unroll 5
        for (int n = 0; n < NGT; n++) {
            float4 bx = s_box[n];
            float cw = fminf(bx.z, px2) - fmaxf(bx.x, px1);
            float ch = fminf(bx.w, py2) - fmaxf(bx.y, py1);
            float I  = fmaxf(cw, 0.0f) * fmaxf(ch, 0.0f);
            float S  = s_m3sa[n] * (-1.0f / 3.0f) + paeps;  // gt_area + pa + eps
            if (I * bS > bI * S) { bI = I; bS = S; bidx = n; }
        }

        float4 g = s_gt[bidx];
        float d0 = t0 - g.x;
        float d1 = t1 - g.y;
        float d2 = t2 - g.z;
        float d3 = t3 - g.w;
        float dc = 5.0f * conf - 5.0f;
        loss = d0 * d0 + d1 * d1 + d2 * d2 + d3 * d3 + dc * dc;

        // class NLL (logits ~N(0,1): unshifted logsumexp is safe)
        int idx = (int)s_cls[bidx];
        const float* cl = base + (size_t)5 * HW;
        float ssum = 0.0f;
        for (int c = 0; c < NC; c++)
            ssum += __expf(cl[(size_t)c * HW]);
        float lt = cl[(size_t)idx * HW];
        loss += __logf(ssum) - lt;
    } else {
        loss = conf * conf;
    }

    // block reduction in double
    double v = (double)loss;
    #pragma unroll
    for (int off = 16; off; off >>= 1)
        v += __shfl_down_sync(0xffffffffu, v, off);

    const int lane = threadIdx.x & 31;
    const int wid  = threadIdx.x >> 5;
    if (lane == 0) s_red[wid] = v;
    __syncthreads();
    if (threadIdx.x < 32) {
        v = (lane < 8) ? s_red[lane] : 0.0;
        #pragma unroll
        for (int off = 4; off; off >>= 1)
            v += __shfl_down_sync(0xffu, v, off);
    }

    // last-block-reduces (single launch, graph-replay safe)
    if (threadIdx.x == 0) {
        g_part[blockIdx.x] = v;
        __threadfence();
        unsigned int done = atomicAdd(&g_flag, 1u);
        s_last = (done == NBLOCKS - 1);
    }
    __syncthreads();

    if (s_last) {
        double t = 0.0;
        for (int i = threadIdx.x; i < NBLOCKS; i += 256)
            t += g_part[i];
        #pragma unroll
        for (int off = 16; off; off >>= 1)
            t += __shfl_down_sync(0xffffffffu, t, off);
        if (lane == 0) s_red[wid] = t;
        __syncthreads();
        if (threadIdx.x == 0) {
            double tot = 0.0;
            #pragma unroll
            for (int i = 0; i < 8; i++) tot += s_red[i];
            out[0] = (float)tot;
            atomicExch(&g_flag, 0u);
        }
    }
}

extern "C" void kernel_launch(void* const* d_in, const int* in_sizes, int n_in,
                              void* d_out, int out_size)
{
    const float* outp    = (const float*)d_in[0];
    const float* target  = (const float*)d_in[1];
    const float* anchors = (const float*)d_in[2];
    float* out = (float*)d_out;

    rl_loss_kernel<<<NBLOCKS, 256>>>(outp, target, anchors, out);
}